// round 14
// baseline (speedup 1.0000x reference)
#include <cuda_runtime.h>
#include <math.h>

constexpr int NN = 2048;
constexpr int MM = 2048;
constexpr int DD = 16;

constexpr int BT           = 128;      // threads per block (both kernels)
constexpr int ROWS_PER_BLK = 16;       // rows of X per main block
constexpr int COLS_PER_BLK = 2 * BT;   // 256 cols per main block (2/thread)
constexpr int NPAIR        = MM / 2;   // 1024 column pairs

typedef unsigned long long u64;

// ---- packed fp32x2 ops (sm_103a; ptxas never emits FFMA2 from C++) ----
#define FMA2(d, a, b, c) asm("fma.rn.f32x2 %0, %1, %2, %3;" : "=l"(d) : "l"(a), "l"(b), "l"(c))
#define MUL2(d, a, b)    asm("mul.rn.f32x2 %0, %1, %2;"     : "=l"(d) : "l"(a), "l"(b))
#define ADD2(d, a, b)    asm("add.rn.f32x2 %0, %1, %2;"     : "=l"(d) : "l"(a), "l"(b))
#define PACK2(d, lo, hi) asm("mov.b64 %0, {%1, %2};"        : "=l"(d) : "f"(lo), "f"(hi))
#define UNPACK2(lo, hi, s) asm("mov.b64 {%0, %1}, %2;" : "=f"(lo), "=f"(hi) : "l"(s))
#define EX2(d, s)        asm("ex2.approx.f32 %0, %1;"       : "=f"(d) : "f"(s))

#define LOG2E2 0x3FB8AA3B3FB8AA3BULL   // (log2e, log2e)

// ---- scratch (no allocations allowed -> __device__ globals) ----
__device__ ulonglong2 g_Xrow[NN][DD / 2];     // row d-pairs: ((x,x),(x,x)) dup
__device__ float2     g_HP  [NN];             // (hn, pn)
__device__ ulonglong2 g_Acol[NPAIR][DD / 2];  // (A[2q], A[2q+1]), A=(a,b)
__device__ ulonglong2 g_Ucol[NPAIR][DD / 2];  // U = A * w  (w_d = c1 - c2*l2_d)
__device__ float4     g_QH  [NPAIR];          // (Qa, Qb, Ha, Hb)

// ---------------------------------------------------------------------------
// Prep: 3072 work items (2048 rows of X, 1024 col-pairs of X2).
// Softplus params computed once per block via smem.
// ---------------------------------------------------------------------------
__global__ __launch_bounds__(BT)
void prep_kernel(const float* __restrict__ X,
                 const float* __restrict__ X2,
                 const float* __restrict__ uls,
                 const float* __restrict__ uv)
{
    __shared__ float sInv[DD], sL2[DD], sVar;
    const int t = threadIdx.x;

    if (t < DD) {
        float u = uls[t];
        float s = (u > 20.f) ? u : log1pf(expf(u));
        sInv[t] = 1.f / s;
        sL2[t]  = 1.f / (s * s);
    }
    if (t == DD) {
        float u = uv[0];
        sVar = (u > 20.f) ? u : log1pf(expf(u));
    }
    __syncthreads();

    float L = 0.f;
#pragma unroll
    for (int d = 0; d < DD; ++d) L += sL2[d];
    const float var = sVar;
    const float c1  = 2.f * var * L;
    const float c2  = 2.f * var;

    const int i = blockIdx.x * BT + t;

    if (i < NN) {
        // ---- row work ----
        const float4* xr = reinterpret_cast<const float4*>(X + (size_t)i * DD);
        float xl[DD];
        float xs = 0.f, s1 = 0.f;
#pragma unroll
        for (int q = 0; q < DD / 4; ++q) {
            float4 v = xr[q];
            float v0 = v.x * sInv[4*q+0], v1 = v.y * sInv[4*q+1];
            float v2 = v.z * sInv[4*q+2], v3 = v.w * sInv[4*q+3];
            xl[4*q+0] = v0; xl[4*q+1] = v1; xl[4*q+2] = v2; xl[4*q+3] = v3;
            xs += v0*v0 + v1*v1 + v2*v2 + v3*v3;
            s1 += v0*v0*sL2[4*q+0] + v1*v1*sL2[4*q+1]
                + v2*v2*sL2[4*q+2] + v3*v3*sL2[4*q+3];
        }
#pragma unroll
        for (int q = 0; q < DD / 2; ++q) {
            u64 p0; PACK2(p0, xl[2*q+0], xl[2*q+0]);
            u64 p1; PACK2(p1, xl[2*q+1], xl[2*q+1]);
            g_Xrow[i][q] = make_ulonglong2(p0, p1);
        }
        float hn = -0.5f * xs;
        float pn = var * (s1 + ((float)DD - 1.f - xs) * L);
        g_HP[i] = make_float2(hn, pn);
    } else if (i < NN + NPAIR) {
        // ---- column-pair work (cols 2j, 2j+1) ----
        const int j = i - NN;
        const float4* r = reinterpret_cast<const float4*>(X2 + (size_t)(2 * j) * DD);
        float a[DD], b[DD];
        float x2s0 = 0.f, s20 = 0.f, x2s1 = 0.f, s21 = 0.f;
#pragma unroll
        for (int q = 0; q < DD / 4; ++q) {
            float4 va = r[q];
            float4 vb = r[q + DD / 4];
            float a0 = va.x * sInv[4*q+0], a1 = va.y * sInv[4*q+1];
            float a2 = va.z * sInv[4*q+2], a3 = va.w * sInv[4*q+3];
            float b0 = vb.x * sInv[4*q+0], b1 = vb.y * sInv[4*q+1];
            float b2 = vb.z * sInv[4*q+2], b3 = vb.w * sInv[4*q+3];
            a[4*q+0]=a0; a[4*q+1]=a1; a[4*q+2]=a2; a[4*q+3]=a3;
            b[4*q+0]=b0; b[4*q+1]=b1; b[4*q+2]=b2; b[4*q+3]=b3;
            x2s0 += a0*a0 + a1*a1 + a2*a2 + a3*a3;
            x2s1 += b0*b0 + b1*b1 + b2*b2 + b3*b3;
            s20  += a0*a0*sL2[4*q+0] + a1*a1*sL2[4*q+1]
                  + a2*a2*sL2[4*q+2] + a3*a3*sL2[4*q+3];
            s21  += b0*b0*sL2[4*q+0] + b1*b1*sL2[4*q+1]
                  + b2*b2*sL2[4*q+2] + b3*b3*sL2[4*q+3];
        }
#pragma unroll
        for (int q = 0; q < DD / 2; ++q) {
            int d0 = 2*q, d1 = 2*q + 1;
            u64 A0; PACK2(A0, a[d0], b[d0]);
            u64 A1; PACK2(A1, a[d1], b[d1]);
            float w0 = c1 - c2 * sL2[d0];
            float w1 = c1 - c2 * sL2[d1];
            u64 U0; PACK2(U0, a[d0] * w0, b[d0] * w0);
            u64 U1; PACK2(U1, a[d1] * w1, b[d1] * w1);
            g_Acol[j][q] = make_ulonglong2(A0, A1);
            g_Ucol[j][q] = make_ulonglong2(U0, U1);
        }
        g_QH[j] = make_float4(var * (s20 - x2s0 * L),
                              var * (s21 - x2s1 * L),
                              -0.5f * x2s0,
                              -0.5f * x2s1);
    }
}

// ---------------------------------------------------------------------------
// Main: prologue is pure loads; 16 rows x 2 cols per thread, packed f32x2.
// out[n,m] = exp(hn+hm+Xl.X2l) * (P[n]+Q[m]+Xl.(X2l∘w))
// ---------------------------------------------------------------------------
__global__ __launch_bounds__(BT)
void main_kernel(float* __restrict__ out)
{
    __shared__ ulonglong2 sX[ROWS_PER_BLK * (DD / 2)];   // 128 elems, 2KB
    __shared__ float2     sHP[ROWS_PER_BLK];

    const int t  = threadIdx.x;
    const int rb = blockIdx.y * ROWS_PER_BLK;
    const int j  = blockIdx.x * BT + t;    // column pair index; m0 = 2*j

    // ---- prologue: pure loads ----
    sX[t] = g_Xrow[rb + (t >> 3)][t & 7];  // one LDG.128 + STS.128 per thread
    if (t < ROWS_PER_BLK) sHP[t] = g_HP[rb + t];

    u64 A[DD], U[DD];
#pragma unroll
    for (int q = 0; q < DD / 2; ++q) {
        ulonglong2 va = g_Acol[j][q];
        ulonglong2 vu = g_Ucol[j][q];
        A[2*q+0] = va.x; A[2*q+1] = va.y;
        U[2*q+0] = vu.x; U[2*q+1] = vu.y;
    }
    float4 qh = g_QH[j];
    u64 Qp; PACK2(Qp, qh.x, qh.y);
    u64 Hc; PACK2(Hc, qh.z, qh.w);
    __syncthreads();

    // ---- main loop ----
    const u64 log2e2 = LOG2E2;
#pragma unroll 4
    for (int n = 0; n < ROWS_PER_BLK; ++n) {
        const ulonglong2* xv = sX + n * (DD / 2);
        u64 p0 = 0, p1 = 0, w0 = 0, w1 = 0;   // split chains
#pragma unroll
        for (int q = 0; q < DD / 2; ++q) {
            ulonglong2 xx = xv[q];             // broadcast LDS.128
            FMA2(p0, xx.x, A[2*q+0], p0);  FMA2(w0, xx.x, U[2*q+0], w0);
            FMA2(p1, xx.y, A[2*q+1], p1);  FMA2(w1, xx.y, U[2*q+1], w1);
        }
        u64 d0;  ADD2(d0, p0, p1);
        u64 du;  ADD2(du, w0, w1);

        float2 hp = sHP[n];                    // broadcast LDS.64
        u64 h2; PACK2(h2, hp.x, hp.x);
        u64 q2; PACK2(q2, hp.y, hp.y);

        u64 arg; ADD2(arg, d0, Hc); ADD2(arg, arg, h2);
        MUL2(arg, arg, log2e2);
        float g0, g1; UNPACK2(g0, g1, arg);
        float e0, e1; EX2(e0, g0); EX2(e1, g1);

        u64 poly; ADD2(poly, du, Qp); ADD2(poly, poly, q2);
        u64 E; PACK2(E, e0, e1);
        u64 o; MUL2(o, E, poly);

        *reinterpret_cast<u64*>(out + (size_t)(rb + n) * MM + 2 * j) = o;
    }
}

// ---------------------------------------------------------------------------
extern "C" void kernel_launch(void* const* d_in, const int* in_sizes, int n_in,
                              void* d_out, int out_size)
{
    const float* X   = (const float*)d_in[0];   // (2048,16)
    const float* X2  = (const float*)d_in[1];   // (2048,16)
    const float* uls = (const float*)d_in[2];   // (16,)
    const float* uv  = (const float*)d_in[3];   // (1,)
    float* out = (float*)d_out;                 // (2048,2048)

    prep_kernel<<<(NN + NPAIR + BT - 1) / BT, BT>>>(X, X2, uls, uv);  // 24 blocks

    dim3 grid(MM / COLS_PER_BLK, NN / ROWS_PER_BLK);  // (8, 128) = 1024 blocks
    main_kernel<<<grid, BT>>>(out);
}

// round 15
// speedup vs baseline: 1.3219x; 1.3219x over previous
#include <cuda_runtime.h>
#include <math.h>

constexpr int NN = 2048;
constexpr int MM = 2048;
constexpr int DD = 16;

constexpr int BT           = 128;      // threads per block
constexpr int ROWS_PER_BLK = 32;       // rows of X per block
constexpr int COLS_PER_BLK = 2 * BT;   // 256 cols per block (2/thread)

typedef unsigned long long u64;

// ---- packed fp32x2 ops (sm_103a; ptxas never emits FFMA2 from C++) ----
#define FMA2(d, a, b, c) asm("fma.rn.f32x2 %0, %1, %2, %3;" : "=l"(d) : "l"(a), "l"(b), "l"(c))
#define MUL2(d, a, b)    asm("mul.rn.f32x2 %0, %1, %2;"     : "=l"(d) : "l"(a), "l"(b))
#define ADD2(d, a, b)    asm("add.rn.f32x2 %0, %1, %2;"     : "=l"(d) : "l"(a), "l"(b))
#define PACK2(d, lo, hi) asm("mov.b64 %0, {%1, %2};"        : "=l"(d) : "f"(lo), "f"(hi))
#define UNPACK2(lo, hi, s) asm("mov.b64 {%0, %1}, %2;" : "=f"(lo), "=f"(hi) : "l"(s))
#define EX2(d, s)        asm("ex2.approx.f32 %0, %1;"       : "=f"(d) : "f"(s))

#define LOG2E2 0x3FB8AA3B3FB8AA3BULL   // (log2e, log2e)

// ---------------------------------------------------------------------------
// out[n,m] = exp(hn + hm + Xl_n.X2l_m) * (P[n] + Q[m] + Xl_n.(X2l_m ∘ w))
//   w_d = c1 - c2*l2_d,  c1 = 2*var*L,  c2 = 2*var,  L = sum(l2)
// Single kernel. Block: 32 rows x 256 cols. Grid (8,64)=512 blocks, 2048 warps.
// Warp 0: hyperparams. Warp 1: row prep. All: packed column transform.
// ---------------------------------------------------------------------------
__global__ __launch_bounds__(BT)
void fused_kernel(const float* __restrict__ X,
                  const float* __restrict__ X2,
                  const float* __restrict__ uls,
                  const float* __restrict__ uv,
                  float* __restrict__ out)
{
    __shared__ __align__(16) u64 sX[ROWS_PER_BLK * DD];   // (x,x) dup pairs, 4KB
    __shared__ float2 sHP[ROWS_PER_BLK];                  // (hn, pn)
    __shared__ u64   sInv2[DD];                           // (inv,inv)
    __shared__ u64   sL22 [DD];                           // (l2,l2)
    __shared__ u64   sW2  [DD];                           // (w,w)
    __shared__ float4 sC;                                 // (var, L, c1, c2)

    const int t  = threadIdx.x;
    const int rb = blockIdx.y * ROWS_PER_BLK;
    const int j  = blockIdx.x * BT + t;        // column-pair index; m0 = 2*j

    // ---- stage 1 (warp 0): softplus of 17 hyperparams ----
    if (t < DD) {
        float u = uls[t];
        float s = (u > 20.f) ? u : log1pf(expf(u));
        float inv = 1.f / s;
        float l2  = inv * inv;
        u64 p;
        PACK2(p, inv, inv); sInv2[t] = p;
        PACK2(p, l2,  l2);  sL22[t]  = p;
    }
    if (t == DD) {
        float u = uv[0];
        float var = (u > 20.f) ? u : log1pf(expf(u));
        sC.x = var;
    }
    __syncthreads();

    // ---- stage 2 (warp 0): L, c1, c2, w-vector ----
    if (t < DD) {
        float L = 0.f;
#pragma unroll
        for (int d = 0; d < DD; ++d)
            L += __uint_as_float((unsigned)(sL22[d] & 0xFFFFFFFFu));
        float var = sC.x;
        float c1 = 2.f * var * L;
        float c2 = 2.f * var;
        float l2t = __uint_as_float((unsigned)(sL22[t] & 0xFFFFFFFFu));
        float w = c1 - c2 * l2t;
        u64 p; PACK2(p, w, w); sW2[t] = p;
        if (t == 0) { sC.y = L; sC.z = c1; sC.w = c2; }
    }

    // ---- stage 2 (warp 1): row prep, one row per lane ----
    if (t >= 32 && t < 32 + ROWS_PER_BLK) {
        const int r = t - 32;
        const float4* xr = reinterpret_cast<const float4*>(X + (size_t)(rb + r) * DD);
        float4 v0 = xr[0], v1 = xr[1], v2 = xr[2], v3 = xr[3];
        float xl[DD];
        {
            // scalar inv from low half of dup entries
#pragma unroll
            for (int q = 0; q < 4; ++q) {
                float4 v = (q == 0) ? v0 : (q == 1) ? v1 : (q == 2) ? v2 : v3;
                xl[4*q+0] = v.x * __uint_as_float((unsigned)(sInv2[4*q+0] & 0xFFFFFFFFu));
                xl[4*q+1] = v.y * __uint_as_float((unsigned)(sInv2[4*q+1] & 0xFFFFFFFFu));
                xl[4*q+2] = v.z * __uint_as_float((unsigned)(sInv2[4*q+2] & 0xFFFFFFFFu));
                xl[4*q+3] = v.w * __uint_as_float((unsigned)(sInv2[4*q+3] & 0xFFFFFFFFu));
            }
        }
        float xs = 0.f, s1 = 0.f;
#pragma unroll
        for (int d = 0; d < DD; ++d) {
            float l2d = __uint_as_float((unsigned)(sL22[d] & 0xFFFFFFFFu));
            xs += xl[d] * xl[d];
            s1 = fmaf(xl[d] * xl[d], l2d, s1);
        }
#pragma unroll
        for (int d = 0; d < DD; ++d) {
            u64 p; PACK2(p, xl[d], xl[d]);
            sX[r * DD + d] = p;
        }
        // var & L not yet published by warp0? They are: stage-1 sync gave sC.x;
        // L recomputed locally (cheap, avoids extra sync)
        float L = 0.f;
#pragma unroll
        for (int d = 0; d < DD; ++d)
            L += __uint_as_float((unsigned)(sL22[d] & 0xFFFFFFFFu));
        float var = sC.x;
        float hn = -0.5f * xs;
        float pn = var * (s1 + ((float)DD - 1.f - xs) * L);
        sHP[r] = make_float2(hn, pn);
    }
    __syncthreads();

    // ---- stage 3 (all threads): packed column transform ----
    u64 A[DD], U[DD];
    u64 Qp, Hc;
    {
        const float4* r4 = reinterpret_cast<const float4*>(X2 + (size_t)(2 * j) * DD);
        float4 ra0 = r4[0], ra1 = r4[1], ra2 = r4[2], ra3 = r4[3];   // col a
        float4 rb0 = r4[4], rb1 = r4[5], rb2 = r4[6], rb3 = r4[7];   // col b

        u64 x2s = 0, s2 = 0;
#pragma unroll
        for (int q = 0; q < 4; ++q) {
            float4 va = (q == 0) ? ra0 : (q == 1) ? ra1 : (q == 2) ? ra2 : ra3;
            float4 vb = (q == 0) ? rb0 : (q == 1) ? rb1 : (q == 2) ? rb2 : rb3;
#pragma unroll
            for (int jj = 0; jj < 4; ++jj) {
                int d = 4 * q + jj;
                float fa = (jj == 0) ? va.x : (jj == 1) ? va.y : (jj == 2) ? va.z : va.w;
                float fb = (jj == 0) ? vb.x : (jj == 1) ? vb.y : (jj == 2) ? vb.z : vb.w;
                u64 raw; PACK2(raw, fa, fb);
                u64 Ad;  MUL2(Ad, raw, sInv2[d]);     // A = x2/ls  (a,b)
                A[d] = Ad;
                MUL2(U[d], Ad, sW2[d]);               // U = A*w
                u64 A2;  MUL2(A2, Ad, Ad);            // A^2
                ADD2(x2s, x2s, A2);                   // sum A^2
                FMA2(s2, A2, sL22[d], s2);            // sum A^2*l2
            }
        }
        float var = sC.x, L = sC.y;
        u64 nL2;  PACK2(nL2, -L, -L);
        u64 var2; PACK2(var2, var, var);
        u64 half2; { float hneg = -0.5f; PACK2(half2, hneg, hneg); }
        u64 qa; FMA2(qa, x2s, nL2, s2);               // s2 - x2s*L
        MUL2(Qp, qa, var2);                           // Q pair
        MUL2(Hc, x2s, half2);                         // -0.5*x2s pair
    }
    __syncthreads();

    // ---- main loop: 32 rows, 2 cols per thread, packed f32x2 ----
    const u64 log2e2 = LOG2E2;
#pragma unroll 2
    for (int n = 0; n < ROWS_PER_BLK; ++n) {
        const ulonglong2* xv = reinterpret_cast<const ulonglong2*>(sX + n * DD);
        u64 p0 = 0, p1 = 0, w0 = 0, w1 = 0;   // 4 split chains, 8 FMA2 each
#pragma unroll
        for (int q = 0; q < DD / 2; ++q) {
            ulonglong2 xx = xv[q];             // broadcast LDS.128
            FMA2(p0, xx.x, A[2*q+0], p0);  FMA2(w0, xx.x, U[2*q+0], w0);
            FMA2(p1, xx.y, A[2*q+1], p1);  FMA2(w1, xx.y, U[2*q+1], w1);
        }
        u64 d0;  ADD2(d0, p0, p1);
        u64 du;  ADD2(du, w0, w1);

        float2 hp = sHP[n];                    // broadcast LDS.64
        u64 h2; PACK2(h2, hp.x, hp.x);
        u64 q2; PACK2(q2, hp.y, hp.y);

        u64 arg; ADD2(arg, d0, Hc); ADD2(arg, arg, h2);
        MUL2(arg, arg, log2e2);
        float g0, g1; UNPACK2(g0, g1, arg);
        float e0, e1; EX2(e0, g0); EX2(e1, g1);

        u64 poly; ADD2(poly, du, Qp); ADD2(poly, poly, q2);
        u64 E; PACK2(E, e0, e1);
        u64 o; MUL2(o, E, poly);

        *reinterpret_cast<u64*>(out + (size_t)(rb + n) * MM + 2 * j) = o;
    }
}

// ---------------------------------------------------------------------------
extern "C" void kernel_launch(void* const* d_in, const int* in_sizes, int n_in,
                              void* d_out, int out_size)
{
    const float* X   = (const float*)d_in[0];   // (2048,16)
    const float* X2  = (const float*)d_in[1];   // (2048,16)
    const float* uls = (const float*)d_in[2];   // (16,)
    const float* uv  = (const float*)d_in[3];   // (1,)
    float* out = (float*)d_out;                 // (2048,2048)

    dim3 grid(MM / COLS_PER_BLK, NN / ROWS_PER_BLK);  // (8, 64) = 512 blocks
    fused_kernel<<<grid, BT>>>(X, X2, uls, uv, out);
}

// round 16
// speedup vs baseline: 2.0090x; 1.5197x over previous
#include <cuda_runtime.h>
#include <math.h>

constexpr int NN = 2048;
constexpr int MM = 2048;
constexpr int DD = 16;

constexpr int BT           = 128;       // threads per block
constexpr int ROWS_PER_BLK = 64;        // rows of X per block (R6-proven)
constexpr int COLS_PER_BLK = 2 * BT;    // 256 cols per block (2/thread)
constexpr int ROW_STRIDE   = DD / 2 + 1; // 9 ulonglong2 per row record

typedef unsigned long long u64;

// ---- packed fp32x2 ops (sm_103a; ptxas never emits FFMA2 from C++) ----
#define FMA2(d, a, b, c) asm("fma.rn.f32x2 %0, %1, %2, %3;" : "=l"(d) : "l"(a), "l"(b), "l"(c))
#define MUL2(d, a, b)    asm("mul.rn.f32x2 %0, %1, %2;"     : "=l"(d) : "l"(a), "l"(b))
#define ADD2(d, a, b)    asm("add.rn.f32x2 %0, %1, %2;"     : "=l"(d) : "l"(a), "l"(b))
#define PACK2(d, lo, hi) asm("mov.b64 %0, {%1, %2};"        : "=l"(d) : "f"(lo), "f"(hi))
#define UNPACK2(lo, hi, s) asm("mov.b64 {%0, %1}, %2;" : "=f"(lo), "=f"(hi) : "l"(s))
#define EX2(d, s)        asm("ex2.approx.f32 %0, %1;"       : "=f"(d) : "f"(s))

#define LOG2E      1.4426950408889634f
#define INV_LOG2E  0.6931471805599453f

// ---------------------------------------------------------------------------
// out[n,m] = exp2(d0' + Hc' + hn') * (P[n] + Q[m] + dw)
//   sX rows hold xl*log2e (dup pairs)  ->  p-chain gives d0*log2e directly
//   U' = A*w/log2e  ->  w-chain on the scaled rows still gives dw exactly
//   Hc' = -0.5*x2s*log2e (per thread), hn' = -0.5*xs*log2e (per row)
//   w_d = c1 - c2*l2_d,  c1 = 2*var*L,  c2 = 2*var,  L = sum(l2)
// Block: 64 rows x 256 cols; grid (8,32)=256 blocks (R6 geometry).
// ---------------------------------------------------------------------------
__global__ __launch_bounds__(BT)
void fused_kernel(const float* __restrict__ X,
                  const float* __restrict__ X2,
                  const float* __restrict__ uls,
                  const float* __restrict__ uv,
                  float* __restrict__ out)
{
    // row record: 8 x (xl*log2e, xl*log2e) pairs + 1 x ((hn',hn'),(pn,pn))
    __shared__ __align__(16) ulonglong2 sX[ROWS_PER_BLK * ROW_STRIDE];  // 9KB
    __shared__ float sInv[DD];
    __shared__ float sL2 [DD];
    __shared__ float sVar;

    const int t  = threadIdx.x;
    const int rb = blockIdx.y * ROWS_PER_BLK;
    const int m0 = blockIdx.x * COLS_PER_BLK + 2 * t;

    // ---- phase 1: softplus of hyperparams (17 scalars) ----
    if (t < DD) {
        float u = uls[t];
        float s = (u > 20.f) ? u : log1pf(expf(u));
        sInv[t] = 1.f / s;
        sL2[t]  = 1.f / (s * s);
    }
    if (t == DD) {
        float u = uv[0];
        sVar = (u > 20.f) ? u : log1pf(expf(u));
    }
    __syncthreads();

    float L = 0.f;
#pragma unroll
    for (int d = 0; d < DD; ++d) L += sL2[d];
    const float var = sVar;
    const float c1  = 2.f * var * L;
    const float c2  = 2.f * var;

    // ---- phase 2a: row prep, one row per thread (t < 64), scalar ----
    if (t < ROWS_PER_BLK) {
        const float4* xr = reinterpret_cast<const float4*>(X + (size_t)(rb + t) * DD);
        float xl[DD];
        float xs = 0.f, s1 = 0.f;
#pragma unroll
        for (int q = 0; q < DD / 4; ++q) {
            float4 v = xr[q];
            float v0 = v.x * sInv[4*q+0], v1 = v.y * sInv[4*q+1];
            float v2 = v.z * sInv[4*q+2], v3 = v.w * sInv[4*q+3];
            xl[4*q+0] = v0; xl[4*q+1] = v1; xl[4*q+2] = v2; xl[4*q+3] = v3;
            xs += v0*v0 + v1*v1 + v2*v2 + v3*v3;
            s1 += v0*v0*sL2[4*q+0] + v1*v1*sL2[4*q+1]
                + v2*v2*sL2[4*q+2] + v3*v3*sL2[4*q+3];
        }
#pragma unroll
        for (int q = 0; q < DD / 2; ++q) {
            float e0 = xl[2*q+0] * LOG2E;
            float e1 = xl[2*q+1] * LOG2E;
            u64 p0; PACK2(p0, e0, e0);
            u64 p1; PACK2(p1, e1, e1);
            sX[t * ROW_STRIDE + q] = make_ulonglong2(p0, p1);
        }
        float hn = -0.5f * xs * LOG2E;                       // prescaled
        float pn = var * (s1 + ((float)DD - 1.f - xs) * L);  // not scaled
        u64 hh; PACK2(hh, hn, hn);
        u64 pp; PACK2(pp, pn, pn);
        sX[t * ROW_STRIDE + DD / 2] = make_ulonglong2(hh, pp);
    }

    // ---- phase 2b: per-thread column transform (scalar, R6-style) ----
    u64 A[DD], U[DD];
    u64 Qp, Hc;
    {
        const float4* r = reinterpret_cast<const float4*>(X2 + (size_t)m0 * DD);
        float x2s0 = 0.f, s20 = 0.f, x2s1 = 0.f, s21 = 0.f;
#pragma unroll
        for (int q = 0; q < DD / 4; ++q) {
            float4 va = r[q];
            float4 vb = r[q + DD / 4];
#pragma unroll
            for (int jj = 0; jj < 4; ++jj) {
                int d = 4 * q + jj;
                float inv = sInv[d], l2d = sL2[d];
                float aj = ((jj==0)?va.x:(jj==1)?va.y:(jj==2)?va.z:va.w) * inv;
                float bj = ((jj==0)?vb.x:(jj==1)?vb.y:(jj==2)?vb.z:vb.w) * inv;
                x2s0 += aj * aj;  s20 += aj * aj * l2d;
                x2s1 += bj * bj;  s21 += bj * bj * l2d;
                PACK2(A[d], aj, bj);
                float w = (c1 - c2 * l2d) * INV_LOG2E;       // compensate row scale
                PACK2(U[d], aj * w, bj * w);
            }
        }
        PACK2(Qp, var * (s20 - x2s0 * L), var * (s21 - x2s1 * L));
        PACK2(Hc, -0.5f * x2s0 * LOG2E, -0.5f * x2s1 * LOG2E);
    }
    __syncthreads();

    // ---- main loop: 64 rows, 2 cols per thread ----
#pragma unroll 2
    for (int n = 0; n < ROWS_PER_BLK; ++n) {
        const ulonglong2* xv = sX + n * ROW_STRIDE;
        // accumulator-init folds: p-chain starts at Hc', w-chain at Qp
        u64 p0 = Hc, w0 = Qp, p1 = 0, w1 = 0;
#pragma unroll
        for (int q = 0; q < DD / 2; ++q) {
            ulonglong2 xx = xv[q];             // broadcast LDS.128
            FMA2(p0, xx.x, A[2*q+0], p0);  FMA2(w0, xx.x, U[2*q+0], w0);
            FMA2(p1, xx.y, A[2*q+1], p1);  FMA2(w1, xx.y, U[2*q+1], w1);
        }
        ulonglong2 hp = xv[DD / 2];            // (hn' dup, pn dup) LDS.128

        u64 arg; ADD2(arg, p0, p1); ADD2(arg, arg, hp.x);
        float g0, g1; UNPACK2(g0, g1, arg);
        float e0, e1; EX2(e0, g0); EX2(e1, g1);

        u64 poly; ADD2(poly, w0, w1); ADD2(poly, poly, hp.y);
        u64 E; PACK2(E, e0, e1);
        u64 o; MUL2(o, E, poly);

        *reinterpret_cast<u64*>(out + (size_t)(rb + n) * MM + m0) = o;
    }
}

// ---------------------------------------------------------------------------
extern "C" void kernel_launch(void* const* d_in, const int* in_sizes, int n_in,
                              void* d_out, int out_size)
{
    const float* X   = (const float*)d_in[0];   // (2048,16)
    const float* X2  = (const float*)d_in[1];   // (2048,16)
    const float* uls = (const float*)d_in[2];   // (16,)
    const float* uv  = (const float*)d_in[3];   // (1,)
    float* out = (float*)d_out;                 // (2048,2048)

    dim3 grid(MM / COLS_PER_BLK, NN / ROWS_PER_BLK);  // (8, 32) = 256 blocks
    fused_kernel<<<grid, BT>>>(X, X2, uls, uv, out);
}

// round 17
// speedup vs baseline: 2.2420x; 1.1160x over previous
#include <cuda_runtime.h>
#include <math.h>

constexpr int NN = 2048;
constexpr int MM = 2048;
constexpr int DD = 16;

constexpr int BT           = 128;      // threads per block
constexpr int ROWS_PER_BLK = 32;       // rows of X per block
constexpr int COLS_PER_BLK = 2 * BT;   // 256 cols per block (2 adjacent/thread)

#define LOG2E      1.4426950408889634f
#define INV_LOG2E  0.6931471805599453f

#define EX2(d, s) asm("ex2.approx.f32 %0, %1;" : "=f"(d) : "f"(s))

// ---------------------------------------------------------------------------
// out[n,m] = exp2(d0' + hn') * (pn + dw)      [scalar FFMA hot loop]
//   sXl rows hold xl*log2e  ->  A-chain yields (Xl.X2l + hc)*log2e directly
//     (accumulator initialized with hc' = -0.5*x2s*log2e, per-thread const)
//   U = A ∘ w / log2e  ->  U-chain on scaled rows yields dw exactly
//     (accumulator initialized with Q[m], per-thread const -> epilogue is tiny)
//   w_d = c1 - c2*l2_d,  c1 = 2*var*L,  c2 = 2*var,  L = sum(l2)
// Block: 32 rows x 256 cols. Grid (8,64) = 512 blocks = 2048 warps.
// ---------------------------------------------------------------------------
__global__ __launch_bounds__(BT)
void fused_kernel(const float* __restrict__ X,
                  const float* __restrict__ X2,
                  const float* __restrict__ uls,
                  const float* __restrict__ uv,
                  float* __restrict__ out)
{
    __shared__ __align__(16) float sXl[ROWS_PER_BLK * DD];  // xl*log2e, 2KB
    __shared__ float2 sHP[ROWS_PER_BLK];                    // (hn*log2e, pn)
    __shared__ float  sInv[DD];
    __shared__ float  sL2 [DD];
    __shared__ float  sVar;

    const int t  = threadIdx.x;
    const int rb = blockIdx.y * ROWS_PER_BLK;
    const int m0 = blockIdx.x * COLS_PER_BLK + 2 * t;

    // ---- phase 1: softplus of hyperparams (17 scalars) ----
    if (t < DD) {
        float u = uls[t];
        float s = (u > 20.f) ? u : log1pf(expf(u));
        sInv[t] = 1.f / s;
        sL2[t]  = 1.f / (s * s);
    }
    if (t == DD) {
        float u = uv[0];
        sVar = (u > 20.f) ? u : log1pf(expf(u));
    }
    __syncthreads();

    float L = 0.f;
#pragma unroll
    for (int d = 0; d < DD; ++d) L += sL2[d];
    const float var = sVar;
    const float c1  = 2.f * var * L;
    const float c2  = 2.f * var;

    // ---- phase 2a: row prep, one row per lane of warp 0 ----
    if (t < ROWS_PER_BLK) {
        const float4* xr = reinterpret_cast<const float4*>(X + (size_t)(rb + t) * DD);
        float xl[DD];
        float xs = 0.f, s1 = 0.f;
#pragma unroll
        for (int q = 0; q < DD / 4; ++q) {
            float4 v = xr[q];
            float v0 = v.x * sInv[4*q+0], v1 = v.y * sInv[4*q+1];
            float v2 = v.z * sInv[4*q+2], v3 = v.w * sInv[4*q+3];
            xl[4*q+0] = v0; xl[4*q+1] = v1; xl[4*q+2] = v2; xl[4*q+3] = v3;
            xs += v0*v0 + v1*v1 + v2*v2 + v3*v3;
            s1 += v0*v0*sL2[4*q+0] + v1*v1*sL2[4*q+1]
                + v2*v2*sL2[4*q+2] + v3*v3*sL2[4*q+3];
        }
        float4* srow = reinterpret_cast<float4*>(sXl + t * DD);
#pragma unroll
        for (int q = 0; q < DD / 4; ++q)
            srow[q] = make_float4(xl[4*q+0] * LOG2E, xl[4*q+1] * LOG2E,
                                  xl[4*q+2] * LOG2E, xl[4*q+3] * LOG2E);
        float hn = -0.5f * xs * LOG2E;                       // prescaled
        float pn = var * (s1 + ((float)DD - 1.f - xs) * L);
        sHP[t] = make_float2(hn, pn);
    }

    // ---- phase 2b: per-thread column transform (cols m0, m0+1), scalar ----
    float A0[DD], U0[DD], A1[DD], U1[DD];
    float hc0, q0, hc1, q1;
    {
        const float4* r = reinterpret_cast<const float4*>(X2 + (size_t)m0 * DD);
        float x2s0 = 0.f, s20 = 0.f, x2s1 = 0.f, s21 = 0.f;
#pragma unroll
        for (int q = 0; q < DD / 4; ++q) {
            float4 va = r[q];
            float4 vb = r[q + DD / 4];
#pragma unroll
            for (int jj = 0; jj < 4; ++jj) {
                int d = 4 * q + jj;
                float inv = sInv[d], l2d = sL2[d];
                float aj = ((jj==0)?va.x:(jj==1)?va.y:(jj==2)?va.z:va.w) * inv;
                float bj = ((jj==0)?vb.x:(jj==1)?vb.y:(jj==2)?vb.z:vb.w) * inv;
                x2s0 += aj * aj;  s20 = fmaf(aj * aj, l2d, s20);
                x2s1 += bj * bj;  s21 = fmaf(bj * bj, l2d, s21);
                float w = (c1 - c2 * l2d) * INV_LOG2E;       // compensate row scale
                A0[d] = aj;  U0[d] = aj * w;
                A1[d] = bj;  U1[d] = bj * w;
            }
        }
        hc0 = -0.5f * x2s0 * LOG2E;  q0 = var * (s20 - x2s0 * L);
        hc1 = -0.5f * x2s1 * LOG2E;  q1 = var * (s21 - x2s1 * L);
    }
    __syncthreads();

    // ---- main loop: 32 rows, 2 cols per thread, scalar FFMA ----
#pragma unroll 2
    for (int n = 0; n < ROWS_PER_BLK; ++n) {
        const float4* xv = reinterpret_cast<const float4*>(sXl + n * DD);
        // accumulator-init folds: exp-args start at hc', dw chains start at Q[m]
        float d0a = hc0, dwa = q0, d0b = hc1, dwb = q1;
#pragma unroll
        for (int q = 0; q < DD / 4; ++q) {
            float4 x4 = xv[q];                 // broadcast LDS.128
            d0a = fmaf(x4.x, A0[4*q+0], d0a);  dwa = fmaf(x4.x, U0[4*q+0], dwa);
            d0a = fmaf(x4.y, A0[4*q+1], d0a);  dwa = fmaf(x4.y, U0[4*q+1], dwa);
            d0a = fmaf(x4.z, A0[4*q+2], d0a);  dwa = fmaf(x4.z, U0[4*q+2], dwa);
            d0a = fmaf(x4.w, A0[4*q+3], d0a);  dwa = fmaf(x4.w, U0[4*q+3], dwa);
            d0b = fmaf(x4.x, A1[4*q+0], d0b);  dwb = fmaf(x4.x, U1[4*q+0], dwb);
            d0b = fmaf(x4.y, A1[4*q+1], d0b);  dwb = fmaf(x4.y, U1[4*q+1], dwb);
            d0b = fmaf(x4.z, A1[4*q+2], d0b);  dwb = fmaf(x4.z, U1[4*q+2], dwb);
            d0b = fmaf(x4.w, A1[4*q+3], d0b);  dwb = fmaf(x4.w, U1[4*q+3], dwb);
        }
        float2 hp = sHP[n];                    // broadcast LDS.64: (hn', pn)
        float e0, e1;
        EX2(e0, d0a + hp.x);
        EX2(e1, d0b + hp.x);
        float2 o;
        o.x = e0 * (hp.y + dwa);
        o.y = e1 * (hp.y + dwb);
        *reinterpret_cast<float2*>(out + (size_t)(rb + n) * MM + m0) = o;
    }
}

// ---------------------------------------------------------------------------
extern "C" void kernel_launch(void* const* d_in, const int* in_sizes, int n_in,
                              void* d_out, int out_size)
{
    const float* X   = (const float*)d_in[0];   // (2048,16)
    const float* X2  = (const float*)d_in[1];   // (2048,16)
    const float* uls = (const float*)d_in[2];   // (16,)
    const float* uv  = (const float*)d_in[3];   // (1,)
    float* out = (float*)d_out;                 // (2048,2048)

    dim3 grid(MM / COLS_PER_BLK, NN / ROWS_PER_BLK);  // (8, 64) = 512 blocks
    fused_kernel<<<grid, BT>>>(X, X2, uls, uv, out);
}